// round 12
// baseline (speedup 1.0000x reference)
#include <cuda_runtime.h>
#include <cuda_bf16.h>
#include <math_constants.h>
#include <cstdint>

#define E_TOT 50000
#define E_PAD 50048
#define DD 128
#define HH 256
#define BB 8
#define KTOP 10
#define TILE_M 128
#define NCHUNK 16
#define CAP 1024
#define MARGIN 0.15f
#define N_TILES ((E_TOT + TILE_M - 1) / TILE_M)   // 391

__device__ float g_ph[BB * HH];
__device__ float g_part[2][BB][E_PAD];
__device__ float g_sum[BB][E_PAD];
__device__ float g_cs[BB * NCHUNK * KTOP];
__device__ int   g_cand[BB][CAP];
__device__ int   g_cnt[BB];
__device__ float g_cand_score[BB][CAP];

// ---------------------------------------------------------------------------
__device__ __forceinline__ void mma_bf16(float c[4], const uint32_t a[4],
                                         uint32_t b0, uint32_t b1) {
    asm volatile(
        "mma.sync.aligned.m16n8k16.row.col.f32.bf16.bf16.f32 "
        "{%0,%1,%2,%3}, {%4,%5,%6,%7}, {%8,%9}, {%0,%1,%2,%3};"
        : "+f"(c[0]), "+f"(c[1]), "+f"(c[2]), "+f"(c[3])
        : "r"(a[0]), "r"(a[1]), "r"(a[2]), "r"(a[3]), "r"(b0), "r"(b1));
}
__device__ __forceinline__ uint32_t pack_bf16(float lo, float hi) {
    return (uint32_t)__bfloat16_as_ushort(__float2bfloat16_rn(lo)) |
           ((uint32_t)__bfloat16_as_ushort(__float2bfloat16_rn(hi)) << 16);
}

// ---------------------------------------------------------------------------
// Kernel 1: ph[b][h]. grid (8, 8), block 256.
// ---------------------------------------------------------------------------
__global__ void ph_kernel(const int* __restrict__ head, const int* __restrict__ rel,
                          const float* __restrict__ ent, const float* __restrict__ relm,
                          const float* __restrict__ W1, const float* __restrict__ b1) {
    __shared__ float red[8][32];
    const int b  = blockIdx.x;
    const int hl = threadIdx.x & 31;
    const int dq = threadIdx.x >> 5;
    const int h  = blockIdx.y * 32 + hl;
    const float* hrow = ent  + (size_t)head[b] * DD;
    const float* rrow = relm + (size_t)rel[b] * DD;
    float acc = 0.f;
#pragma unroll
    for (int dd = 0; dd < 16; ++dd) {
        int d = dq * 16 + dd;
        acc = fmaf(hrow[d], W1[d * HH + h], acc);
        acc = fmaf(rrow[d], W1[(DD + d) * HH + h], acc);
    }
    red[dq][hl] = acc;
    __syncthreads();
    if (threadIdx.x < 32) {
        float s = b1[h];
#pragma unroll
        for (int q = 0; q < 8; ++q) s += red[q][hl];
        g_ph[b * HH + h] = s;
    }
}

// ---------------------------------------------------------------------------
// Kernel 2: PASS A — single-product bf16 approx GEMM + fused relu-score.
// grid (391, 2). nw halves combined in smem; one g_part slot per nh.
// ---------------------------------------------------------------------------
#define PA_STRIDE 68
#define SA_A 0
#define SA_B (128 * PA_STRIDE)
#define SA_PH (2 * 128 * PA_STRIDE)
#define SA_W2 (SA_PH + BB * 128)
#define SA_TOT (SA_W2 + 128)        // 18560 words = 74.2 KB

extern __shared__ float smem_f[];

__global__ __launch_bounds__(256, 2)
void scoreA_kernel(const float* __restrict__ ent, const float* __restrict__ W1,
                   const float* __restrict__ W2) {
    const int tid = threadIdx.x;
    const int wid = tid >> 5;
    const int lid = tid & 31;
    const int gID = lid >> 2;
    const int tig = lid & 3;
    const int mw  = wid & 3;
    const int nw  = wid >> 2;
    const int e_base = blockIdx.x * TILE_M;
    const int nh = blockIdx.y;

    uint32_t* A32 = (uint32_t*)(smem_f + SA_A);
    uint32_t* B32 = (uint32_t*)(smem_f + SA_B);
    float* ph_s = smem_f + SA_PH;
    float* w2_s = smem_f + SA_W2;

    for (int idx = tid; idx < BB * 128; idx += 256) {
        int b = idx >> 7, col = idx & 127;
        ph_s[idx] = g_ph[b * HH + nh * 128 + col];
    }
    if (tid < 128) w2_s[tid] = W2[nh * 128 + tid];

    // stage A: 128 m x 64 kpairs
#pragma unroll
    for (int it = 0; it < 16; ++it) {
        int idx = it * 256 + tid;
        int m = idx >> 5;
        int q = idx & 31;
        float4 v = make_float4(0.f, 0.f, 0.f, 0.f);
        if (e_base + m < E_TOT)
            v = *(const float4*)(ent + (size_t)(e_base + m) * DD + q * 4);
        A32[m * PA_STRIDE + 2 * q]     = pack_bf16(v.x, v.y);
        A32[m * PA_STRIDE + 2 * q + 1] = pack_bf16(v.z, v.w);
    }
    // stage B transposed
    {
        const float* W1t = W1 + 2 * DD * HH;
#pragma unroll
        for (int it = 0; it < 8; ++it) {
            int idx = it * 256 + tid;
            int kp = idx >> 5;
            int n4 = idx & 31;
            float4 v0 = *(const float4*)(W1t + (size_t)(2 * kp) * HH + nh * 128 + n4 * 4);
            float4 v1 = *(const float4*)(W1t + (size_t)(2 * kp + 1) * HH + nh * 128 + n4 * 4);
            B32[(n4 * 4 + 0) * PA_STRIDE + kp] = pack_bf16(v0.x, v1.x);
            B32[(n4 * 4 + 1) * PA_STRIDE + kp] = pack_bf16(v0.y, v1.y);
            B32[(n4 * 4 + 2) * PA_STRIDE + kp] = pack_bf16(v0.z, v1.z);
            B32[(n4 * 4 + 3) * PA_STRIDE + kp] = pack_bf16(v0.w, v1.w);
        }
    }
    __syncthreads();

    float acc[2][8][4];
#pragma unroll
    for (int mt = 0; mt < 2; ++mt)
#pragma unroll
        for (int nt = 0; nt < 8; ++nt)
#pragma unroll
            for (int q = 0; q < 4; ++q) acc[mt][nt][q] = 0.f;

#pragma unroll
    for (int st = 0; st < 8; ++st) {
        const int kp0 = st * 8;
        uint32_t a[2][4];
#pragma unroll
        for (int mt = 0; mt < 2; ++mt) {
            int r = mw * 32 + mt * 16 + gID;
            a[mt][0] = A32[r * PA_STRIDE + kp0 + tig];
            a[mt][1] = A32[(r + 8) * PA_STRIDE + kp0 + tig];
            a[mt][2] = A32[r * PA_STRIDE + kp0 + tig + 4];
            a[mt][3] = A32[(r + 8) * PA_STRIDE + kp0 + tig + 4];
        }
#pragma unroll
        for (int nt = 0; nt < 8; ++nt) {
            int n = nw * 64 + nt * 8 + gID;
            uint32_t b0 = B32[n * PA_STRIDE + kp0 + tig];
            uint32_t b1 = B32[n * PA_STRIDE + kp0 + tig + 4];
            mma_bf16(acc[0][nt], a[0], b0, b1);
            mma_bf16(acc[1][nt], a[1], b0, b1);
        }
    }

    // epilogue: approx relu-score, quad-reduce, nw-combine in smem
    float2 w2v[8];
#pragma unroll
    for (int nt = 0; nt < 8; ++nt)
        w2v[nt] = *(float2*)(w2_s + nw * 64 + nt * 8 + tig * 2);

    __syncthreads();                       // A32/B32 reads done; safe to reuse
    float* part_s = smem_f + SA_A;         // [2(nw)][BB][128]

#pragma unroll
    for (int b = 0; b < BB; ++b) {
        float s00 = 0.f, s01 = 0.f, s10 = 0.f, s11 = 0.f;
#pragma unroll
        for (int nt = 0; nt < 8; ++nt) {
            float2 p2 = *(float2*)(ph_s + b * 128 + nw * 64 + nt * 8 + tig * 2);
            float wx = w2v[nt].x, wy = w2v[nt].y;
            s00 = fmaf(fmaxf(acc[0][nt][0] + p2.x, 0.f), wx, s00);
            s00 = fmaf(fmaxf(acc[0][nt][1] + p2.y, 0.f), wy, s00);
            s01 = fmaf(fmaxf(acc[0][nt][2] + p2.x, 0.f), wx, s01);
            s01 = fmaf(fmaxf(acc[0][nt][3] + p2.y, 0.f), wy, s01);
            s10 = fmaf(fmaxf(acc[1][nt][0] + p2.x, 0.f), wx, s10);
            s10 = fmaf(fmaxf(acc[1][nt][1] + p2.y, 0.f), wy, s10);
            s11 = fmaf(fmaxf(acc[1][nt][2] + p2.x, 0.f), wx, s11);
            s11 = fmaf(fmaxf(acc[1][nt][3] + p2.y, 0.f), wy, s11);
        }
#pragma unroll
        for (int off = 1; off <= 2; off <<= 1) {
            s00 += __shfl_xor_sync(0xffffffffu, s00, off);
            s01 += __shfl_xor_sync(0xffffffffu, s01, off);
            s10 += __shfl_xor_sync(0xffffffffu, s10, off);
            s11 += __shfl_xor_sync(0xffffffffu, s11, off);
        }
        if (tig == 0) {
            int r0 = mw * 32 + gID;
            int r1 = mw * 32 + 16 + gID;
            part_s[(nw * BB + b) * 128 + r0]     = s00;
            part_s[(nw * BB + b) * 128 + r0 + 8] = s01;
            part_s[(nw * BB + b) * 128 + r1]     = s10;
            part_s[(nw * BB + b) * 128 + r1 + 8] = s11;
        }
    }
    __syncthreads();

#pragma unroll
    for (int it = 0; it < 4; ++it) {
        int idx = it * 256 + tid;          // b*128 + row
        int b = idx >> 7, row = idx & 127;
        g_part[nh][b][e_base + row] =
            part_s[(0 * BB + b) * 128 + row] + part_s[(1 * BB + b) * 128 + row];
    }
}

// ---------------------------------------------------------------------------
// Kernel 3: per-(batch, chunk) top-10 approx VALUES; materialize g_sum.
// grid (8, 16), block 256.
// ---------------------------------------------------------------------------
__global__ void topkA_kernel() {
    const int b = blockIdx.x;
    const int c = blockIdx.y;
    const int tid = threadIdx.x;
    if (c == 0 && tid == 0) g_cnt[b] = 0;

    const int cbeg = c * (E_TOT / NCHUNK);
    const int cend = cbeg + (E_TOT / NCHUNK);

    float sc[KTOP];
#pragma unroll
    for (int j = 0; j < KTOP; ++j) sc[j] = -CUDART_INF_F;

    for (int e = cbeg + tid; e < cend; e += 256) {
        float s = g_part[0][b][e] + g_part[1][b][e];
        g_sum[b][e] = s;
        if (s > sc[KTOP - 1]) {
            int p = KTOP - 1;
            while (p > 0 && s > sc[p - 1]) { sc[p] = sc[p - 1]; --p; }
            sc[p] = s;
        }
    }

    __shared__ float ssc[256 * KTOP];
#pragma unroll
    for (int j = 0; j < KTOP; ++j) ssc[tid * KTOP + j] = sc[j];
    __syncthreads();

    for (int stride = 128; stride > 0; stride >>= 1) {
        if (tid < stride) {
            float* A  = &ssc[tid * KTOP];
            float* Bv = &ssc[(tid + stride) * KTOP];
            float msc[KTOP];
            int p = 0, q = 0;
#pragma unroll
            for (int j = 0; j < KTOP; ++j) {
                if (A[p] >= Bv[q]) { msc[j] = A[p]; ++p; }
                else               { msc[j] = Bv[q]; ++q; }
            }
#pragma unroll
            for (int j = 0; j < KTOP; ++j) A[j] = msc[j];
        }
        __syncthreads();
    }
    if (tid < KTOP) g_cs[(b * NCHUNK + c) * KTOP + tid] = ssc[tid];
}

// ---------------------------------------------------------------------------
// Kernel 4: threshold + candidate compaction (reads g_sum only).
// grid (8, 16), block 256.
// ---------------------------------------------------------------------------
__global__ void compact_kernel() {
    const int b = blockIdx.x;
    const int c = blockIdx.y;
    const int tid = threadIdx.x;
    __shared__ float vals[256];

    vals[tid] = (tid < NCHUNK * KTOP) ? g_cs[b * NCHUNK * KTOP + tid] : -CUDART_INF_F;
    __syncthreads();
    for (int k = 2; k <= 256; k <<= 1) {
        for (int j = k >> 1; j > 0; j >>= 1) {
            int ixj = tid ^ j;
            if (ixj > tid) {
                bool up = ((tid & k) == 0);
                float s1 = vals[tid], s2 = vals[ixj];
                if ((s1 > s2) != up) { vals[tid] = s2; vals[ixj] = s1; }
            }
            __syncthreads();
        }
    }
    const float thr = vals[KTOP - 1] - MARGIN;

    const int cbeg = c * (E_TOT / NCHUNK);
    const int cend = cbeg + (E_TOT / NCHUNK);
    for (int e = cbeg + tid; e < cend; e += 256) {
        float s = g_sum[b][e];
        if (s >= thr) {
            int pos = atomicAdd(&g_cnt[b], 1);
            if (pos < CAP) g_cand[b][pos] = e;
        }
    }
}

// ---------------------------------------------------------------------------
// Kernel 5: EXACT rescore of candidates. grid (8, 16), block 256.
// ---------------------------------------------------------------------------
#define RS_ENT 0
#define RS_W1 (DD * 64)
#define RS_PH (RS_W1 + 64 * HH)
#define RS_W2 (RS_PH + HH)
#define RS_TOT (RS_W2 + HH)

__global__ __launch_bounds__(256, 2)
void rescore_kernel(const float* __restrict__ ent, const float* __restrict__ W1,
                    const float* __restrict__ W2, const float* __restrict__ b2) {
    const int b = blockIdx.x;
    const int tile = blockIdx.y;
    const int tid = threadIdx.x;
    const int cnt = min(g_cnt[b], CAP);

    if (tile * 64 >= cnt) {
        if (tid < 64) g_cand_score[b][tile * 64 + tid] = -CUDART_INF_F;
        return;
    }

    float* entT = smem_f + RS_ENT;
    float* w1t_s = smem_f + RS_W1;
    float* ph_s = smem_f + RS_PH;
    float* w2_s = smem_f + RS_W2;

    for (int idx = tid; idx < (DD / 4) * 64; idx += 256) {
        int d4 = idx >> 6;
        int i  = idx & 63;
        int slot = tile * 64 + i;
        int e = (slot < cnt) ? g_cand[b][slot] : 0;
        float4 v = *(const float4*)(ent + (size_t)e * DD + d4 * 4);
        entT[(d4 * 4 + 0) * 64 + i] = v.x;
        entT[(d4 * 4 + 1) * 64 + i] = v.y;
        entT[(d4 * 4 + 2) * 64 + i] = v.z;
        entT[(d4 * 4 + 3) * 64 + i] = v.w;
    }
    if (tid < HH) { ph_s[tid] = g_ph[b * HH + tid]; w2_s[tid] = W2[tid]; }

    const int tx = tid & 31;
    const int ty = tid >> 5;
    float acc[8][8];
#pragma unroll
    for (int i = 0; i < 8; ++i)
#pragma unroll
        for (int j = 0; j < 8; ++j) acc[i][j] = 0.f;

    const float* W1t = W1 + 2 * DD * HH;
    for (int kt = 0; kt < 2; ++kt) {
        __syncthreads();
        for (int idx = tid; idx < 64 * HH / 4; idx += 256)
            *(float4*)(w1t_s + idx * 4) = *(const float4*)(W1t + kt * 64 * HH + idx * 4);
        __syncthreads();
#pragma unroll 2
        for (int dd = 0; dd < 64; ++dd) {
            const int d = kt * 64 + dd;
            float w[8], a[8];
            *(float4*)&w[0] = *(float4*)(w1t_s + dd * HH + tx * 4);
            *(float4*)&w[4] = *(float4*)(w1t_s + dd * HH + 128 + tx * 4);
            *(float4*)&a[0] = *(float4*)(entT + d * 64 + ty * 8);
            *(float4*)&a[4] = *(float4*)(entT + d * 64 + ty * 8 + 4);
#pragma unroll
            for (int i = 0; i < 8; ++i)
#pragma unroll
                for (int j = 0; j < 8; ++j)
                    acc[i][j] = fmaf(a[i], w[j], acc[i][j]);
        }
    }

    const float b2v = b2[0];
    float w2v[8], phv[8];
    *(float4*)&w2v[0] = *(float4*)(w2_s + tx * 4);
    *(float4*)&w2v[4] = *(float4*)(w2_s + 128 + tx * 4);
    *(float4*)&phv[0] = *(float4*)(ph_s + tx * 4);
    *(float4*)&phv[4] = *(float4*)(ph_s + 128 + tx * 4);

#pragma unroll
    for (int i = 0; i < 8; ++i) {
        float s = 0.f;
#pragma unroll
        for (int j = 0; j < 8; ++j)
            s = fmaf(fmaxf(acc[i][j] + phv[j], 0.f), w2v[j], s);
#pragma unroll
        for (int off = 16; off > 0; off >>= 1)
            s += __shfl_xor_sync(0xffffffffu, s, off);
        if (tx == 0) {
            int slot = tile * 64 + ty * 8 + i;
            g_cand_score[b][slot] = (slot < cnt) ? (s + b2v) : -CUDART_INF_F;
        }
    }
}

// ---------------------------------------------------------------------------
// Kernel 6: final top-10 over candidates. grid (8), block 256.
// ---------------------------------------------------------------------------
__global__ void topkF_kernel(float* __restrict__ out) {
    const int b = blockIdx.x;
    const int tid = threadIdx.x;

    float sc[KTOP];
    int   si[KTOP];
#pragma unroll
    for (int j = 0; j < KTOP; ++j) { sc[j] = -CUDART_INF_F; si[j] = 0x7fffffff; }

#pragma unroll
    for (int q = 0; q < CAP / 256; ++q) {
        int slot = q * 256 + tid;
        float s = g_cand_score[b][slot];
        int   e = g_cand[b][slot];
        if (s > sc[KTOP - 1] || (s == sc[KTOP - 1] && e < si[KTOP - 1])) {
            int p = KTOP - 1;
            while (p > 0 && (s > sc[p - 1] || (s == sc[p - 1] && e < si[p - 1]))) {
                sc[p] = sc[p - 1]; si[p] = si[p - 1]; --p;
            }
            sc[p] = s; si[p] = e;
        }
    }

    __shared__ float ssc[256 * KTOP];
    __shared__ int   ssi[256 * KTOP];
#pragma unroll
    for (int j = 0; j < KTOP; ++j) { ssc[tid * KTOP + j] = sc[j]; ssi[tid * KTOP + j] = si[j]; }
    __syncthreads();

    for (int stride = 128; stride > 0; stride >>= 1) {
        if (tid < stride) {
            float* A  = &ssc[tid * KTOP];
            int*   Ai = &ssi[tid * KTOP];
            float* Bv = &ssc[(tid + stride) * KTOP];
            int*   Bi = &ssi[(tid + stride) * KTOP];
            float msc[KTOP]; int msi[KTOP];
            int p = 0, q = 0;
#pragma unroll
            for (int j = 0; j < KTOP; ++j) {
                bool takeA = (A[p] > Bv[q]) || (A[p] == Bv[q] && Ai[p] < Bi[q]);
                if (takeA) { msc[j] = A[p]; msi[j] = Ai[p]; ++p; }
                else       { msc[j] = Bv[q]; msi[j] = Bi[q]; ++q; }
            }
#pragma unroll
            for (int j = 0; j < KTOP; ++j) { A[j] = msc[j]; Ai[j] = msi[j]; }
        }
        __syncthreads();
    }

    if (tid < KTOP) {
        out[b * KTOP + tid]             = (float)ssi[tid];   // top_indices
        out[BB * KTOP + b * KTOP + tid] = ssc[tid];          // top_scores
    }
}

// ---------------------------------------------------------------------------
extern "C" void kernel_launch(void* const* d_in, const int* in_sizes, int n_in,
                              void* d_out, int out_size) {
    int base = (n_in >= 3 && in_sizes[2] == 1) ? 3 : 2;

    const int*   head = (const int*)d_in[0];
    const int*   rel  = (const int*)d_in[1];
    const float* ent  = (const float*)d_in[base + 0];
    const float* relm = (const float*)d_in[base + 1];
    const float* W1   = (const float*)d_in[base + 2];
    const float* b1   = (const float*)d_in[base + 3];
    const float* W2   = (const float*)d_in[base + 4];
    const float* b2   = (const float*)d_in[base + 5];
    float* out = (float*)d_out;

    cudaFuncSetAttribute(scoreA_kernel, cudaFuncAttributeMaxDynamicSharedMemorySize,
                         SA_TOT * 4);
    cudaFuncSetAttribute(rescore_kernel, cudaFuncAttributeMaxDynamicSharedMemorySize,
                         RS_TOT * 4);

    ph_kernel<<<dim3(BB, 8), 256>>>(head, rel, ent, relm, W1, b1);
    scoreA_kernel<<<dim3(N_TILES, 2), 256, SA_TOT * 4>>>(ent, W1, W2);
    topkA_kernel<<<dim3(BB, NCHUNK), 256>>>();
    compact_kernel<<<dim3(BB, NCHUNK), 256>>>();
    rescore_kernel<<<dim3(BB, CAP / 64), 256, RS_TOT * 4>>>(ent, W1, W2, b2);
    topkF_kernel<<<BB, 256>>>(out);
}

// round 13
// speedup vs baseline: 1.0423x; 1.0423x over previous
#include <cuda_runtime.h>
#include <cuda_bf16.h>
#include <math_constants.h>
#include <cstdint>

#define E_TOT 50000
#define E_PAD 50048
#define DD 128
#define HH 256
#define BB 8
#define KTOP 10
#define TILE_M 128
#define NCHUNK 16
#define CHUNK (E_TOT / NCHUNK)      // 3125
#define CAP 1024
#define MARGIN 0.15f
#define N_TILES ((E_TOT + TILE_M - 1) / TILE_M)   // 391

__device__ float g_ph[BB * HH];
__device__ float g_part[2][BB][E_PAD];
__device__ int   g_cand[BB][CAP];
__device__ int   g_cnt[BB];
__device__ float g_cand_score[BB][CAP];

// ---------------------------------------------------------------------------
__device__ __forceinline__ void mma_bf16(float c[4], const uint32_t a[4],
                                         uint32_t b0, uint32_t b1) {
    asm volatile(
        "mma.sync.aligned.m16n8k16.row.col.f32.bf16.bf16.f32 "
        "{%0,%1,%2,%3}, {%4,%5,%6,%7}, {%8,%9}, {%0,%1,%2,%3};"
        : "+f"(c[0]), "+f"(c[1]), "+f"(c[2]), "+f"(c[3])
        : "r"(a[0]), "r"(a[1]), "r"(a[2]), "r"(a[3]), "r"(b0), "r"(b1));
}
__device__ __forceinline__ uint32_t pack_bf16(float lo, float hi) {
    return (uint32_t)__bfloat16_as_ushort(__float2bfloat16_rn(lo)) |
           ((uint32_t)__bfloat16_as_ushort(__float2bfloat16_rn(hi)) << 16);
}

// ---------------------------------------------------------------------------
// Kernel 1: ph[b][h]. grid (8, 8), block 256. Also zeroes g_cnt.
// ---------------------------------------------------------------------------
__global__ void ph_kernel(const int* __restrict__ head, const int* __restrict__ rel,
                          const float* __restrict__ ent, const float* __restrict__ relm,
                          const float* __restrict__ W1, const float* __restrict__ b1) {
    __shared__ float red[8][32];
    const int b  = blockIdx.x;
    if (blockIdx.y == 0 && threadIdx.x == 0) g_cnt[b] = 0;
    const int hl = threadIdx.x & 31;
    const int dq = threadIdx.x >> 5;
    const int h  = blockIdx.y * 32 + hl;
    const float* hrow = ent  + (size_t)head[b] * DD;
    const float* rrow = relm + (size_t)rel[b] * DD;
    float acc = 0.f;
#pragma unroll
    for (int dd = 0; dd < 16; ++dd) {
        int d = dq * 16 + dd;
        acc = fmaf(hrow[d], W1[d * HH + h], acc);
        acc = fmaf(rrow[d], W1[(DD + d) * HH + h], acc);
    }
    red[dq][hl] = acc;
    __syncthreads();
    if (threadIdx.x < 32) {
        float s = b1[h];
#pragma unroll
        for (int q = 0; q < 8; ++q) s += red[q][hl];
        g_ph[b * HH + h] = s;
    }
}

// ---------------------------------------------------------------------------
// Kernel 2: PASS A — single-product bf16 approx GEMM + fused relu-score.
// grid (391, 2). nw halves combined in smem; one g_part slot per nh.
// ---------------------------------------------------------------------------
#define PA_STRIDE 68
#define SA_A 0
#define SA_B (128 * PA_STRIDE)
#define SA_PH (2 * 128 * PA_STRIDE)
#define SA_W2 (SA_PH + BB * 128)
#define SA_TOT (SA_W2 + 128)        // 18560 words = 74.2 KB

extern __shared__ float smem_f[];

__global__ __launch_bounds__(256, 2)
void scoreA_kernel(const float* __restrict__ ent, const float* __restrict__ W1,
                   const float* __restrict__ W2) {
    const int tid = threadIdx.x;
    const int wid = tid >> 5;
    const int lid = tid & 31;
    const int gID = lid >> 2;
    const int tig = lid & 3;
    const int mw  = wid & 3;
    const int nw  = wid >> 2;
    const int e_base = blockIdx.x * TILE_M;
    const int nh = blockIdx.y;

    uint32_t* A32 = (uint32_t*)(smem_f + SA_A);
    uint32_t* B32 = (uint32_t*)(smem_f + SA_B);
    float* ph_s = smem_f + SA_PH;
    float* w2_s = smem_f + SA_W2;

    for (int idx = tid; idx < BB * 128; idx += 256) {
        int b = idx >> 7, col = idx & 127;
        ph_s[idx] = g_ph[b * HH + nh * 128 + col];
    }
    if (tid < 128) w2_s[tid] = W2[nh * 128 + tid];

#pragma unroll
    for (int it = 0; it < 16; ++it) {
        int idx = it * 256 + tid;
        int m = idx >> 5;
        int q = idx & 31;
        float4 v = make_float4(0.f, 0.f, 0.f, 0.f);
        if (e_base + m < E_TOT)
            v = *(const float4*)(ent + (size_t)(e_base + m) * DD + q * 4);
        A32[m * PA_STRIDE + 2 * q]     = pack_bf16(v.x, v.y);
        A32[m * PA_STRIDE + 2 * q + 1] = pack_bf16(v.z, v.w);
    }
    {
        const float* W1t = W1 + 2 * DD * HH;
#pragma unroll
        for (int it = 0; it < 8; ++it) {
            int idx = it * 256 + tid;
            int kp = idx >> 5;
            int n4 = idx & 31;
            float4 v0 = *(const float4*)(W1t + (size_t)(2 * kp) * HH + nh * 128 + n4 * 4);
            float4 v1 = *(const float4*)(W1t + (size_t)(2 * kp + 1) * HH + nh * 128 + n4 * 4);
            B32[(n4 * 4 + 0) * PA_STRIDE + kp] = pack_bf16(v0.x, v1.x);
            B32[(n4 * 4 + 1) * PA_STRIDE + kp] = pack_bf16(v0.y, v1.y);
            B32[(n4 * 4 + 2) * PA_STRIDE + kp] = pack_bf16(v0.z, v1.z);
            B32[(n4 * 4 + 3) * PA_STRIDE + kp] = pack_bf16(v0.w, v1.w);
        }
    }
    __syncthreads();

    float acc[2][8][4];
#pragma unroll
    for (int mt = 0; mt < 2; ++mt)
#pragma unroll
        for (int nt = 0; nt < 8; ++nt)
#pragma unroll
            for (int q = 0; q < 4; ++q) acc[mt][nt][q] = 0.f;

#pragma unroll
    for (int st = 0; st < 8; ++st) {
        const int kp0 = st * 8;
        uint32_t a[2][4];
#pragma unroll
        for (int mt = 0; mt < 2; ++mt) {
            int r = mw * 32 + mt * 16 + gID;
            a[mt][0] = A32[r * PA_STRIDE + kp0 + tig];
            a[mt][1] = A32[(r + 8) * PA_STRIDE + kp0 + tig];
            a[mt][2] = A32[r * PA_STRIDE + kp0 + tig + 4];
            a[mt][3] = A32[(r + 8) * PA_STRIDE + kp0 + tig + 4];
        }
#pragma unroll
        for (int nt = 0; nt < 8; ++nt) {
            int n = nw * 64 + nt * 8 + gID;
            uint32_t b0 = B32[n * PA_STRIDE + kp0 + tig];
            uint32_t b1 = B32[n * PA_STRIDE + kp0 + tig + 4];
            mma_bf16(acc[0][nt], a[0], b0, b1);
            mma_bf16(acc[1][nt], a[1], b0, b1);
        }
    }

    float2 w2v[8];
#pragma unroll
    for (int nt = 0; nt < 8; ++nt)
        w2v[nt] = *(float2*)(w2_s + nw * 64 + nt * 8 + tig * 2);

    __syncthreads();
    float* part_s = smem_f + SA_A;         // [2(nw)][BB][128]

#pragma unroll
    for (int b = 0; b < BB; ++b) {
        float s00 = 0.f, s01 = 0.f, s10 = 0.f, s11 = 0.f;
#pragma unroll
        for (int nt = 0; nt < 8; ++nt) {
            float2 p2 = *(float2*)(ph_s + b * 128 + nw * 64 + nt * 8 + tig * 2);
            float wx = w2v[nt].x, wy = w2v[nt].y;
            s00 = fmaf(fmaxf(acc[0][nt][0] + p2.x, 0.f), wx, s00);
            s00 = fmaf(fmaxf(acc[0][nt][1] + p2.y, 0.f), wy, s00);
            s01 = fmaf(fmaxf(acc[0][nt][2] + p2.x, 0.f), wx, s01);
            s01 = fmaf(fmaxf(acc[0][nt][3] + p2.y, 0.f), wy, s01);
            s10 = fmaf(fmaxf(acc[1][nt][0] + p2.x, 0.f), wx, s10);
            s10 = fmaf(fmaxf(acc[1][nt][1] + p2.y, 0.f), wy, s10);
            s11 = fmaf(fmaxf(acc[1][nt][2] + p2.x, 0.f), wx, s11);
            s11 = fmaf(fmaxf(acc[1][nt][3] + p2.y, 0.f), wy, s11);
        }
#pragma unroll
        for (int off = 1; off <= 2; off <<= 1) {
            s00 += __shfl_xor_sync(0xffffffffu, s00, off);
            s01 += __shfl_xor_sync(0xffffffffu, s01, off);
            s10 += __shfl_xor_sync(0xffffffffu, s10, off);
            s11 += __shfl_xor_sync(0xffffffffu, s11, off);
        }
        if (tig == 0) {
            int r0 = mw * 32 + gID;
            int r1 = mw * 32 + 16 + gID;
            part_s[(nw * BB + b) * 128 + r0]     = s00;
            part_s[(nw * BB + b) * 128 + r0 + 8] = s01;
            part_s[(nw * BB + b) * 128 + r1]     = s10;
            part_s[(nw * BB + b) * 128 + r1 + 8] = s11;
        }
    }
    __syncthreads();

#pragma unroll
    for (int it = 0; it < 4; ++it) {
        int idx = it * 256 + tid;
        int b = idx >> 7, row = idx & 127;
        g_part[nh][b][e_base + row] =
            part_s[(0 * BB + b) * 128 + row] + part_s[(1 * BB + b) * 128 + row];
    }
}

// ---------------------------------------------------------------------------
// Kernel 3: fused screen — chunk top-10 + chunk-local threshold + compaction.
// grid (8, 16), block 256. Sums cached in smem; single pass over g_part.
// Chunk-local thr = chunk10th − MARGIN ≤ global10th − MARGIN: safe superset.
// ---------------------------------------------------------------------------
__global__ void screen_kernel() {
    const int b = blockIdx.x;
    const int c = blockIdx.y;
    const int tid = threadIdx.x;
    const int cbeg = c * CHUNK;

    __shared__ float sums[CHUNK + 3];
    __shared__ float ssc[256 * KTOP];

    float sc[KTOP];
#pragma unroll
    for (int j = 0; j < KTOP; ++j) sc[j] = -CUDART_INF_F;

    for (int i = tid; i < CHUNK; i += 256) {
        int e = cbeg + i;
        float s = g_part[0][b][e] + g_part[1][b][e];
        sums[i] = s;
        if (s > sc[KTOP - 1]) {
            int p = KTOP - 1;
            while (p > 0 && s > sc[p - 1]) { sc[p] = sc[p - 1]; --p; }
            sc[p] = s;
        }
    }

#pragma unroll
    for (int j = 0; j < KTOP; ++j) ssc[tid * KTOP + j] = sc[j];
    __syncthreads();

    for (int stride = 128; stride > 0; stride >>= 1) {
        if (tid < stride) {
            float* A  = &ssc[tid * KTOP];
            float* Bv = &ssc[(tid + stride) * KTOP];
            float msc[KTOP];
            int p = 0, q = 0;
#pragma unroll
            for (int j = 0; j < KTOP; ++j) {
                if (A[p] >= Bv[q]) { msc[j] = A[p]; ++p; }
                else               { msc[j] = Bv[q]; ++q; }
            }
#pragma unroll
            for (int j = 0; j < KTOP; ++j) A[j] = msc[j];
        }
        __syncthreads();
    }

    const float thr = ssc[KTOP - 1] - MARGIN;

    for (int i = tid; i < CHUNK; i += 256) {
        if (sums[i] >= thr) {
            int pos = atomicAdd(&g_cnt[b], 1);
            if (pos < CAP) g_cand[b][pos] = cbeg + i;
        }
    }
}

// ---------------------------------------------------------------------------
// Kernel 4: EXACT rescore of candidates. grid (8, 16), block 256.
// ---------------------------------------------------------------------------
#define RS_ENT 0
#define RS_W1 (DD * 64)
#define RS_PH (RS_W1 + 64 * HH)
#define RS_W2 (RS_PH + HH)
#define RS_TOT (RS_W2 + HH)

__global__ __launch_bounds__(256, 2)
void rescore_kernel(const float* __restrict__ ent, const float* __restrict__ W1,
                    const float* __restrict__ W2, const float* __restrict__ b2) {
    const int b = blockIdx.x;
    const int tile = blockIdx.y;
    const int tid = threadIdx.x;
    const int cnt = min(g_cnt[b], CAP);

    if (tile * 64 >= cnt) {
        if (tid < 64) g_cand_score[b][tile * 64 + tid] = -CUDART_INF_F;
        return;
    }

    float* entT = smem_f + RS_ENT;
    float* w1t_s = smem_f + RS_W1;
    float* ph_s = smem_f + RS_PH;
    float* w2_s = smem_f + RS_W2;

    for (int idx = tid; idx < (DD / 4) * 64; idx += 256) {
        int d4 = idx >> 6;
        int i  = idx & 63;
        int slot = tile * 64 + i;
        int e = (slot < cnt) ? g_cand[b][slot] : 0;
        float4 v = *(const float4*)(ent + (size_t)e * DD + d4 * 4);
        entT[(d4 * 4 + 0) * 64 + i] = v.x;
        entT[(d4 * 4 + 1) * 64 + i] = v.y;
        entT[(d4 * 4 + 2) * 64 + i] = v.z;
        entT[(d4 * 4 + 3) * 64 + i] = v.w;
    }
    if (tid < HH) { ph_s[tid] = g_ph[b * HH + tid]; w2_s[tid] = W2[tid]; }

    const int tx = tid & 31;
    const int ty = tid >> 5;
    float acc[8][8];
#pragma unroll
    for (int i = 0; i < 8; ++i)
#pragma unroll
        for (int j = 0; j < 8; ++j) acc[i][j] = 0.f;

    const float* W1t = W1 + 2 * DD * HH;
    for (int kt = 0; kt < 2; ++kt) {
        __syncthreads();
        for (int idx = tid; idx < 64 * HH / 4; idx += 256)
            *(float4*)(w1t_s + idx * 4) = *(const float4*)(W1t + kt * 64 * HH + idx * 4);
        __syncthreads();
#pragma unroll 2
        for (int dd = 0; dd < 64; ++dd) {
            const int d = kt * 64 + dd;
            float w[8], a[8];
            *(float4*)&w[0] = *(float4*)(w1t_s + dd * HH + tx * 4);
            *(float4*)&w[4] = *(float4*)(w1t_s + dd * HH + 128 + tx * 4);
            *(float4*)&a[0] = *(float4*)(entT + d * 64 + ty * 8);
            *(float4*)&a[4] = *(float4*)(entT + d * 64 + ty * 8 + 4);
#pragma unroll
            for (int i = 0; i < 8; ++i)
#pragma unroll
                for (int j = 0; j < 8; ++j)
                    acc[i][j] = fmaf(a[i], w[j], acc[i][j]);
        }
    }

    const float b2v = b2[0];
    float w2v[8], phv[8];
    *(float4*)&w2v[0] = *(float4*)(w2_s + tx * 4);
    *(float4*)&w2v[4] = *(float4*)(w2_s + 128 + tx * 4);
    *(float4*)&phv[0] = *(float4*)(ph_s + tx * 4);
    *(float4*)&phv[4] = *(float4*)(ph_s + 128 + tx * 4);

#pragma unroll
    for (int i = 0; i < 8; ++i) {
        float s = 0.f;
#pragma unroll
        for (int j = 0; j < 8; ++j)
            s = fmaf(fmaxf(acc[i][j] + phv[j], 0.f), w2v[j], s);
#pragma unroll
        for (int off = 16; off > 0; off >>= 1)
            s += __shfl_xor_sync(0xffffffffu, s, off);
        if (tx == 0) {
            int slot = tile * 64 + ty * 8 + i;
            g_cand_score[b][slot] = (slot < cnt) ? (s + b2v) : -CUDART_INF_F;
        }
    }
}

// ---------------------------------------------------------------------------
// Kernel 5: final top-10 over candidates. grid (8), block 256.
// ---------------------------------------------------------------------------
__global__ void topkF_kernel(float* __restrict__ out) {
    const int b = blockIdx.x;
    const int tid = threadIdx.x;

    float sc[KTOP];
    int   si[KTOP];
#pragma unroll
    for (int j = 0; j < KTOP; ++j) { sc[j] = -CUDART_INF_F; si[j] = 0x7fffffff; }

#pragma unroll
    for (int q = 0; q < CAP / 256; ++q) {
        int slot = q * 256 + tid;
        float s = g_cand_score[b][slot];
        int   e = g_cand[b][slot];
        if (s > sc[KTOP - 1] || (s == sc[KTOP - 1] && e < si[KTOP - 1])) {
            int p = KTOP - 1;
            while (p > 0 && (s > sc[p - 1] || (s == sc[p - 1] && e < si[p - 1]))) {
                sc[p] = sc[p - 1]; si[p] = si[p - 1]; --p;
            }
            sc[p] = s; si[p] = e;
        }
    }

    __shared__ float ssc[256 * KTOP];
    __shared__ int   ssi[256 * KTOP];
#pragma unroll
    for (int j = 0; j < KTOP; ++j) { ssc[tid * KTOP + j] = sc[j]; ssi[tid * KTOP + j] = si[j]; }
    __syncthreads();

    for (int stride = 128; stride > 0; stride >>= 1) {
        if (tid < stride) {
            float* A  = &ssc[tid * KTOP];
            int*   Ai = &ssi[tid * KTOP];
            float* Bv = &ssc[(tid + stride) * KTOP];
            int*   Bi = &ssi[(tid + stride) * KTOP];
            float msc[KTOP]; int msi[KTOP];
            int p = 0, q = 0;
#pragma unroll
            for (int j = 0; j < KTOP; ++j) {
                bool takeA = (A[p] > Bv[q]) || (A[p] == Bv[q] && Ai[p] < Bi[q]);
                if (takeA) { msc[j] = A[p]; msi[j] = Ai[p]; ++p; }
                else       { msc[j] = Bv[q]; msi[j] = Bi[q]; ++q; }
            }
#pragma unroll
            for (int j = 0; j < KTOP; ++j) { A[j] = msc[j]; Ai[j] = msi[j]; }
        }
        __syncthreads();
    }

    if (tid < KTOP) {
        out[b * KTOP + tid]             = (float)ssi[tid];   // top_indices
        out[BB * KTOP + b * KTOP + tid] = ssc[tid];          // top_scores
    }
}

// ---------------------------------------------------------------------------
extern "C" void kernel_launch(void* const* d_in, const int* in_sizes, int n_in,
                              void* d_out, int out_size) {
    int base = (n_in >= 3 && in_sizes[2] == 1) ? 3 : 2;

    const int*   head = (const int*)d_in[0];
    const int*   rel  = (const int*)d_in[1];
    const float* ent  = (const float*)d_in[base + 0];
    const float* relm = (const float*)d_in[base + 1];
    const float* W1   = (const float*)d_in[base + 2];
    const float* b1   = (const float*)d_in[base + 3];
    const float* W2   = (const float*)d_in[base + 4];
    const float* b2   = (const float*)d_in[base + 5];
    float* out = (float*)d_out;

    cudaFuncSetAttribute(scoreA_kernel, cudaFuncAttributeMaxDynamicSharedMemorySize,
                         SA_TOT * 4);
    cudaFuncSetAttribute(rescore_kernel, cudaFuncAttributeMaxDynamicSharedMemorySize,
                         RS_TOT * 4);

    ph_kernel<<<dim3(BB, 8), 256>>>(head, rel, ent, relm, W1, b1);
    scoreA_kernel<<<dim3(N_TILES, 2), 256, SA_TOT * 4>>>(ent, W1, W2);
    screen_kernel<<<dim3(BB, NCHUNK), 256>>>();
    rescore_kernel<<<dim3(BB, CAP / 64), 256, RS_TOT * 4>>>(ent, W1, W2, b2);
    topkF_kernel<<<BB, 256>>>(out);
}

// round 15
// speedup vs baseline: 1.1050x; 1.0601x over previous
#include <cuda_runtime.h>
#include <cuda_bf16.h>
#include <math_constants.h>
#include <cstdint>

#define E_TOT 50000
#define E_PAD 50048
#define DD 128
#define HH 256
#define BB 8
#define KTOP 10
#define TILE_M 128
#define NCHUNK 16
#define CHUNK (E_TOT / NCHUNK)      // 3125
#define CAP 1024
#define TILE_C 32
#define MARGIN 0.08f
#define N_TILES ((E_TOT + TILE_M - 1) / TILE_M)   // 391

__device__ float g_ph[BB * HH];
__device__ float g_part[2][BB][E_PAD];
__device__ int   g_cand[BB][CAP];
__device__ int   g_cnt[BB];
__device__ float g_cand_score[BB][CAP];

// ---------------------------------------------------------------------------
__device__ __forceinline__ void mma_bf16(float c[4], const uint32_t a[4],
                                         uint32_t b0, uint32_t b1) {
    asm volatile(
        "mma.sync.aligned.m16n8k16.row.col.f32.bf16.bf16.f32 "
        "{%0,%1,%2,%3}, {%4,%5,%6,%7}, {%8,%9}, {%0,%1,%2,%3};"
        : "+f"(c[0]), "+f"(c[1]), "+f"(c[2]), "+f"(c[3])
        : "r"(a[0]), "r"(a[1]), "r"(a[2]), "r"(a[3]), "r"(b0), "r"(b1));
}
__device__ __forceinline__ uint32_t pack_bf16(float lo, float hi) {
    return (uint32_t)__bfloat16_as_ushort(__float2bfloat16_rn(lo)) |
           ((uint32_t)__bfloat16_as_ushort(__float2bfloat16_rn(hi)) << 16);
}

// ---------------------------------------------------------------------------
// Kernel 1: ph[b][h]. grid (8, 8), block 256. Also zeroes g_cnt.
// ---------------------------------------------------------------------------
__global__ void ph_kernel(const int* __restrict__ head, const int* __restrict__ rel,
                          const float* __restrict__ ent, const float* __restrict__ relm,
                          const float* __restrict__ W1, const float* __restrict__ b1) {
    __shared__ float red[8][32];
    const int b  = blockIdx.x;
    if (blockIdx.y == 0 && threadIdx.x == 0) g_cnt[b] = 0;
    const int hl = threadIdx.x & 31;
    const int dq = threadIdx.x >> 5;
    const int h  = blockIdx.y * 32 + hl;
    const float* hrow = ent  + (size_t)head[b] * DD;
    const float* rrow = relm + (size_t)rel[b] * DD;
    float acc = 0.f;
#pragma unroll
    for (int dd = 0; dd < 16; ++dd) {
        int d = dq * 16 + dd;
        acc = fmaf(hrow[d], W1[d * HH + h], acc);
        acc = fmaf(rrow[d], W1[(DD + d) * HH + h], acc);
    }
    red[dq][hl] = acc;
    __syncthreads();
    if (threadIdx.x < 32) {
        float s = b1[h];
#pragma unroll
        for (int q = 0; q < 8; ++q) s += red[q][hl];
        g_ph[b * HH + h] = s;
    }
}

// ---------------------------------------------------------------------------
// Kernel 2: PASS A — single-product bf16 approx GEMM + fused relu-score.
// ---------------------------------------------------------------------------
#define PA_STRIDE 68
#define SA_A 0
#define SA_B (128 * PA_STRIDE)
#define SA_PH (2 * 128 * PA_STRIDE)
#define SA_W2 (SA_PH + BB * 128)
#define SA_TOT (SA_W2 + 128)        // 18560 words = 74.2 KB

extern __shared__ float smem_f[];

__global__ __launch_bounds__(256, 2)
void scoreA_kernel(const float* __restrict__ ent, const float* __restrict__ W1,
                   const float* __restrict__ W2) {
    const int tid = threadIdx.x;
    const int wid = tid >> 5;
    const int lid = tid & 31;
    const int gID = lid >> 2;
    const int tig = lid & 3;
    const int mw  = wid & 3;
    const int nw  = wid >> 2;
    const int e_base = blockIdx.x * TILE_M;
    const int nh = blockIdx.y;

    uint32_t* A32 = (uint32_t*)(smem_f + SA_A);
    uint32_t* B32 = (uint32_t*)(smem_f + SA_B);
    float* ph_s = smem_f + SA_PH;
    float* w2_s = smem_f + SA_W2;

    for (int idx = tid; idx < BB * 128; idx += 256) {
        int b = idx >> 7, col = idx & 127;
        ph_s[idx] = g_ph[b * HH + nh * 128 + col];
    }
    if (tid < 128) w2_s[tid] = W2[nh * 128 + tid];

#pragma unroll
    for (int it = 0; it < 16; ++it) {
        int idx = it * 256 + tid;
        int m = idx >> 5;
        int q = idx & 31;
        float4 v = make_float4(0.f, 0.f, 0.f, 0.f);
        if (e_base + m < E_TOT)
            v = *(const float4*)(ent + (size_t)(e_base + m) * DD + q * 4);
        A32[m * PA_STRIDE + 2 * q]     = pack_bf16(v.x, v.y);
        A32[m * PA_STRIDE + 2 * q + 1] = pack_bf16(v.z, v.w);
    }
    {
        const float* W1t = W1 + 2 * DD * HH;
#pragma unroll
        for (int it = 0; it < 8; ++it) {
            int idx = it * 256 + tid;
            int kp = idx >> 5;
            int n4 = idx & 31;
            float4 v0 = *(const float4*)(W1t + (size_t)(2 * kp) * HH + nh * 128 + n4 * 4);
            float4 v1 = *(const float4*)(W1t + (size_t)(2 * kp + 1) * HH + nh * 128 + n4 * 4);
            B32[(n4 * 4 + 0) * PA_STRIDE + kp] = pack_bf16(v0.x, v1.x);
            B32[(n4 * 4 + 1) * PA_STRIDE + kp] = pack_bf16(v0.y, v1.y);
            B32[(n4 * 4 + 2) * PA_STRIDE + kp] = pack_bf16(v0.z, v1.z);
            B32[(n4 * 4 + 3) * PA_STRIDE + kp] = pack_bf16(v0.w, v1.w);
        }
    }
    __syncthreads();

    float acc[2][8][4];
#pragma unroll
    for (int mt = 0; mt < 2; ++mt)
#pragma unroll
        for (int nt = 0; nt < 8; ++nt)
#pragma unroll
            for (int q = 0; q < 4; ++q) acc[mt][nt][q] = 0.f;

#pragma unroll
    for (int st = 0; st < 8; ++st) {
        const int kp0 = st * 8;
        uint32_t a[2][4];
#pragma unroll
        for (int mt = 0; mt < 2; ++mt) {
            int r = mw * 32 + mt * 16 + gID;
            a[mt][0] = A32[r * PA_STRIDE + kp0 + tig];
            a[mt][1] = A32[(r + 8) * PA_STRIDE + kp0 + tig];
            a[mt][2] = A32[r * PA_STRIDE + kp0 + tig + 4];
            a[mt][3] = A32[(r + 8) * PA_STRIDE + kp0 + tig + 4];
        }
#pragma unroll
        for (int nt = 0; nt < 8; ++nt) {
            int n = nw * 64 + nt * 8 + gID;
            uint32_t b0 = B32[n * PA_STRIDE + kp0 + tig];
            uint32_t b1 = B32[n * PA_STRIDE + kp0 + tig + 4];
            mma_bf16(acc[0][nt], a[0], b0, b1);
            mma_bf16(acc[1][nt], a[1], b0, b1);
        }
    }

    float2 w2v[8];
#pragma unroll
    for (int nt = 0; nt < 8; ++nt)
        w2v[nt] = *(float2*)(w2_s + nw * 64 + nt * 8 + tig * 2);

    __syncthreads();
    float* part_s = smem_f + SA_A;         // [2(nw)][BB][128]

#pragma unroll
    for (int b = 0; b < BB; ++b) {
        float s00 = 0.f, s01 = 0.f, s10 = 0.f, s11 = 0.f;
#pragma unroll
        for (int nt = 0; nt < 8; ++nt) {
            float2 p2 = *(float2*)(ph_s + b * 128 + nw * 64 + nt * 8 + tig * 2);
            float wx = w2v[nt].x, wy = w2v[nt].y;
            s00 = fmaf(fmaxf(acc[0][nt][0] + p2.x, 0.f), wx, s00);
            s00 = fmaf(fmaxf(acc[0][nt][1] + p2.y, 0.f), wy, s00);
            s01 = fmaf(fmaxf(acc[0][nt][2] + p2.x, 0.f), wx, s01);
            s01 = fmaf(fmaxf(acc[0][nt][3] + p2.y, 0.f), wy, s01);
            s10 = fmaf(fmaxf(acc[1][nt][0] + p2.x, 0.f), wx, s10);
            s10 = fmaf(fmaxf(acc[1][nt][1] + p2.y, 0.f), wy, s10);
            s11 = fmaf(fmaxf(acc[1][nt][2] + p2.x, 0.f), wx, s11);
            s11 = fmaf(fmaxf(acc[1][nt][3] + p2.y, 0.f), wy, s11);
        }
#pragma unroll
        for (int off = 1; off <= 2; off <<= 1) {
            s00 += __shfl_xor_sync(0xffffffffu, s00, off);
            s01 += __shfl_xor_sync(0xffffffffu, s01, off);
            s10 += __shfl_xor_sync(0xffffffffu, s10, off);
            s11 += __shfl_xor_sync(0xffffffffu, s11, off);
        }
        if (tig == 0) {
            int r0 = mw * 32 + gID;
            int r1 = mw * 32 + 16 + gID;
            part_s[(nw * BB + b) * 128 + r0]     = s00;
            part_s[(nw * BB + b) * 128 + r0 + 8] = s01;
            part_s[(nw * BB + b) * 128 + r1]     = s10;
            part_s[(nw * BB + b) * 128 + r1 + 8] = s11;
        }
    }
    __syncthreads();

#pragma unroll
    for (int it = 0; it < 4; ++it) {
        int idx = it * 256 + tid;
        int b = idx >> 7, row = idx & 127;
        g_part[nh][b][e_base + row] =
            part_s[(0 * BB + b) * 128 + row] + part_s[(1 * BB + b) * 128 + row];
    }
}

// ---------------------------------------------------------------------------
// Kernel 3: fused screen — chunk top-10 + chunk-local threshold + compaction.
// ---------------------------------------------------------------------------
__global__ void screen_kernel() {
    const int b = blockIdx.x;
    const int c = blockIdx.y;
    const int tid = threadIdx.x;
    const int cbeg = c * CHUNK;

    __shared__ float sums[CHUNK + 3];
    __shared__ float ssc[256 * KTOP];

    float sc[KTOP];
#pragma unroll
    for (int j = 0; j < KTOP; ++j) sc[j] = -CUDART_INF_F;

    for (int i = tid; i < CHUNK; i += 256) {
        int e = cbeg + i;
        float s = g_part[0][b][e] + g_part[1][b][e];
        sums[i] = s;
        if (s > sc[KTOP - 1]) {
            int p = KTOP - 1;
            while (p > 0 && s > sc[p - 1]) { sc[p] = sc[p - 1]; --p; }
            sc[p] = s;
        }
    }

#pragma unroll
    for (int j = 0; j < KTOP; ++j) ssc[tid * KTOP + j] = sc[j];
    __syncthreads();

    for (int stride = 128; stride > 0; stride >>= 1) {
        if (tid < stride) {
            float* A  = &ssc[tid * KTOP];
            float* Bv = &ssc[(tid + stride) * KTOP];
            float msc[KTOP];
            int p = 0, q = 0;
#pragma unroll
            for (int j = 0; j < KTOP; ++j) {
                if (A[p] >= Bv[q]) { msc[j] = A[p]; ++p; }
                else               { msc[j] = Bv[q]; ++q; }
            }
#pragma unroll
            for (int j = 0; j < KTOP; ++j) A[j] = msc[j];
        }
        __syncthreads();
    }

    const float thr = ssc[KTOP - 1] - MARGIN;

    for (int i = tid; i < CHUNK; i += 256) {
        if (sums[i] >= thr) {
            int pos = atomicAdd(&g_cnt[b], 1);
            if (pos < CAP) g_cand[b][pos] = cbeg + i;
        }
    }
}

// ---------------------------------------------------------------------------
// Kernel 4: EXACT rescore. grid (8, CAP/32), block 256, 32 candidates/tile.
// 8 warps x 4 rows each; acc[4][8].
// ---------------------------------------------------------------------------
#define RS_ENT 0                        // entT[d][32]: 4096 f
#define RS_W1 (DD * TILE_C)             // w1t[64][256]: 16384 f
#define RS_PH (RS_W1 + 64 * HH)
#define RS_W2 (RS_PH + HH)
#define RS_TOT (RS_W2 + HH)             // 20992 f = 84 KB

__global__ __launch_bounds__(256, 2)
void rescore_kernel(const float* __restrict__ ent, const float* __restrict__ W1,
                    const float* __restrict__ W2, const float* __restrict__ b2) {
    const int b = blockIdx.x;
    const int tile = blockIdx.y;
    const int tid = threadIdx.x;
    const int cnt = min(g_cnt[b], CAP);

    if (tile * TILE_C >= cnt) {
        if (tid < TILE_C) g_cand_score[b][tile * TILE_C + tid] = -CUDART_INF_F;
        return;
    }

    float* entT = smem_f + RS_ENT;
    float* w1t_s = smem_f + RS_W1;
    float* ph_s = smem_f + RS_PH;
    float* w2_s = smem_f + RS_W2;

    // stage candidate entity rows transposed: entT[d][i], i = 0..31
    for (int idx = tid; idx < (DD / 4) * TILE_C; idx += 256) {
        int d4 = idx >> 5;
        int i  = idx & 31;
        int slot = tile * TILE_C + i;
        int e = (slot < cnt) ? g_cand[b][slot] : 0;
        float4 v = *(const float4*)(ent + (size_t)e * DD + d4 * 4);
        entT[(d4 * 4 + 0) * TILE_C + i] = v.x;
        entT[(d4 * 4 + 1) * TILE_C + i] = v.y;
        entT[(d4 * 4 + 2) * TILE_C + i] = v.z;
        entT[(d4 * 4 + 3) * TILE_C + i] = v.w;
    }
    if (tid < HH) { ph_s[tid] = g_ph[b * HH + tid]; w2_s[tid] = W2[tid]; }

    const int tx = tid & 31;
    const int ty = tid >> 5;
    float acc[4][8];
#pragma unroll
    for (int i = 0; i < 4; ++i)
#pragma unroll
        for (int j = 0; j < 8; ++j) acc[i][j] = 0.f;

    const float* W1t = W1 + 2 * DD * HH;
    for (int kt = 0; kt < 2; ++kt) {
        __syncthreads();
        for (int idx = tid; idx < 64 * HH / 4; idx += 256)
            *(float4*)(w1t_s + idx * 4) = *(const float4*)(W1t + kt * 64 * HH + idx * 4);
        __syncthreads();
#pragma unroll 2
        for (int dd = 0; dd < 64; ++dd) {
            const int d = kt * 64 + dd;
            float w[8], a[4];
            *(float4*)&w[0] = *(float4*)(w1t_s + dd * HH + tx * 4);
            *(float4*)&w[4] = *(float4*)(w1t_s + dd * HH + 128 + tx * 4);
            *(float4*)&a[0] = *(float4*)(entT + d * TILE_C + ty * 4);
#pragma unroll
            for (int i = 0; i < 4; ++i)
#pragma unroll
                for (int j = 0; j < 8; ++j)
                    acc[i][j] = fmaf(a[i], w[j], acc[i][j]);
        }
    }

    const float b2v = b2[0];
    float w2v[8], phv[8];
    *(float4*)&w2v[0] = *(float4*)(w2_s + tx * 4);
    *(float4*)&w2v[4] = *(float4*)(w2_s + 128 + tx * 4);
    *(float4*)&phv[0] = *(float4*)(ph_s + tx * 4);
    *(float4*)&phv[4] = *(float4*)(ph_s + 128 + tx * 4);

#pragma unroll
    for (int i = 0; i < 4; ++i) {
        float s = 0.f;
#pragma unroll
        for (int j = 0; j < 8; ++j)
            s = fmaf(fmaxf(acc[i][j] + phv[j], 0.f), w2v[j], s);
#pragma unroll
        for (int off = 16; off > 0; off >>= 1)
            s += __shfl_xor_sync(0xffffffffu, s, off);
        if (tx == 0) {
            int slot = tile * TILE_C + ty * 4 + i;
            g_cand_score[b][slot] = (slot < cnt) ? (s + b2v) : -CUDART_INF_F;
        }
    }
}

// ---------------------------------------------------------------------------
// Kernel 5: final top-10 over candidates. grid (8), block 256.
// ---------------------------------------------------------------------------
__global__ void topkF_kernel(float* __restrict__ out) {
    const int b = blockIdx.x;
    const int tid = threadIdx.x;

    float sc[KTOP];
    int   si[KTOP];
#pragma unroll
    for (int j = 0; j < KTOP; ++j) { sc[j] = -CUDART_INF_F; si[j] = 0x7fffffff; }

#pragma unroll
    for (int q = 0; q < CAP / 256; ++q) {
        int slot = q * 256 + tid;
        float s = g_cand_score[b][slot];
        int   e = g_cand[b][slot];
        if (s > sc[KTOP - 1] || (s == sc[KTOP - 1] && e < si[KTOP - 1])) {
            int p = KTOP - 1;
            while (p > 0 && (s > sc[p - 1] || (s == sc[p - 1] && e < si[p - 1]))) {
                sc[p] = sc[p - 1]; si[p] = si[p - 1]; --p;
            }
            sc[p] = s; si[p] = e;
        }
    }

    __shared__ float ssc[256 * KTOP];
    __shared__ int   ssi[256 * KTOP];
#pragma unroll
    for (int j = 0; j < KTOP; ++j) { ssc[tid * KTOP + j] = sc[j]; ssi[tid * KTOP + j] = si[j]; }
    __syncthreads();

    for (int stride = 128; stride > 0; stride >>= 1) {
        if (tid < stride) {
            float* A  = &ssc[tid * KTOP];
            int*   Ai = &ssi[tid * KTOP];
            float* Bv = &ssc[(tid + stride) * KTOP];
            int*   Bi = &ssi[(tid + stride) * KTOP];
            float msc[KTOP]; int msi[KTOP];
            int p = 0, q = 0;
#pragma unroll
            for (int j = 0; j < KTOP; ++j) {
                bool takeA = (A[p] > Bv[q]) || (A[p] == Bv[q] && Ai[p] < Bi[q]);
                if (takeA) { msc[j] = A[p]; msi[j] = Ai[p]; ++p; }
                else       { msc[j] = Bv[q]; msi[j] = Bi[q]; ++q; }
            }
#pragma unroll
            for (int j = 0; j < KTOP; ++j) { A[j] = msc[j]; Ai[j] = msi[j]; }
        }
        __syncthreads();
    }

    if (tid < KTOP) {
        out[b * KTOP + tid]             = (float)ssi[tid];   // top_indices
        out[BB * KTOP + b * KTOP + tid] = ssc[tid];          // top_scores
    }
}

// ---------------------------------------------------------------------------
extern "C" void kernel_launch(void* const* d_in, const int* in_sizes, int n_in,
                              void* d_out, int out_size) {
    int base = (n_in >= 3 && in_sizes[2] == 1) ? 3 : 2;

    const int*   head = (const int*)d_in[0];
    const int*   rel  = (const int*)d_in[1];
    const float* ent  = (const float*)d_in[base + 0];
    const float* relm = (const float*)d_in[base + 1];
    const float* W1   = (const float*)d_in[base + 2];
    const float* b1   = (const float*)d_in[base + 3];
    const float* W2   = (const float*)d_in[base + 4];
    const float* b2   = (const float*)d_in[base + 5];
    float* out = (float*)d_out;

    cudaFuncSetAttribute(scoreA_kernel, cudaFuncAttributeMaxDynamicSharedMemorySize,
                         SA_TOT * 4);
    cudaFuncSetAttribute(rescore_kernel, cudaFuncAttributeMaxDynamicSharedMemorySize,
                         RS_TOT * 4);

    ph_kernel<<<dim3(BB, 8), 256>>>(head, rel, ent, relm, W1, b1);
    scoreA_kernel<<<dim3(N_TILES, 2), 256, SA_TOT * 4>>>(ent, W1, W2);
    screen_kernel<<<dim3(BB, NCHUNK), 256>>>();
    rescore_kernel<<<dim3(BB, CAP / TILE_C), 256, RS_TOT * 4>>>(ent, W1, W2, b2);
    topkF_kernel<<<BB, 256>>>(out);
}